// round 7
// baseline (speedup 1.0000x reference)
#include <cuda_runtime.h>
#include <cuda_bf16.h>
#include <mma.h>
#include <math.h>
#include <stdint.h>

using namespace nvcuda;

#define B_ 8
#define T_ 128
#define S_ 256
#define H_ 512

// fp32 scratch
__device__ float g_qs[B_ * T_ * H_];
__device__ float g_hs[B_ * S_ * H_];
// bf16 hi/lo pre-split operands
__device__ __nv_bfloat16 g_qhi[B_ * T_ * H_],  g_qlo[B_ * T_ * H_];
__device__ __nv_bfloat16 g_ehi[B_ * S_ * H_],  g_elo[B_ * S_ * H_];
__device__ __nv_bfloat16 g_wshi[H_ * H_],      g_wslo[H_ * H_];
__device__ __nv_bfloat16 g_whhi[H_ * H_],      g_whlo[H_ * H_];
__device__ __nv_bfloat16 g_wohi[H_ * 2 * H_],  g_wolo[H_ * 2 * H_];
__device__ __nv_bfloat16 g_chi[B_ * T_ * H_],  g_clo[B_ * T_ * H_];

// ---------------------------------------------------------------------------
__device__ __forceinline__ void bsplit(float x, __nv_bfloat16& hi, __nv_bfloat16& lo) {
    hi = __float2bfloat16(x);
    lo = __float2bfloat16(x - __bfloat162float(hi));
}
__device__ __forceinline__ uint32_t smem_u32(const void* p) {
    uint32_t a;
    asm("{ .reg .u64 t; cvta.to.shared.u64 t, %1; cvt.u32.u64 %0, t; }"
        : "=r"(a) : "l"(p));
    return a;
}
__device__ __forceinline__ void cpa16(uint32_t d, const void* s) {
    asm volatile("cp.async.cg.shared.global [%0], [%1], 16;" :: "r"(d), "l"(s));
}
#define CP_COMMIT() asm volatile("cp.async.commit_group;" ::: "memory")
#define CP_WAIT1()  asm volatile("cp.async.wait_group 1;" ::: "memory")
#define CP_WAIT0()  asm volatile("cp.async.wait_group 0;" ::: "memory")

// ---------------------------------------------------------------------------
// convert: split inputs + weights into bf16 hi/lo (one float4 per thread)
// ---------------------------------------------------------------------------
__global__ void __launch_bounds__(256) convert_kernel(
    const float* __restrict__ query, const float* __restrict__ enc,
    const float* __restrict__ W_s, const float* __restrict__ W_h,
    const float* __restrict__ W_out)
{
    const int i4 = blockIdx.x * 256 + threadIdx.x;
    const float* src;
    __nv_bfloat16 *dhi, *dlo;
    int off;
    if (i4 < 131072)      { src = query; dhi = g_qhi;  dlo = g_qlo;  off = i4; }
    else if (i4 < 393216) { src = enc;   dhi = g_ehi;  dlo = g_elo;  off = i4 - 131072; }
    else if (i4 < 458752) { src = W_s;   dhi = g_wshi; dlo = g_wslo; off = i4 - 393216; }
    else if (i4 < 524288) { src = W_h;   dhi = g_whhi; dlo = g_whlo; off = i4 - 458752; }
    else                  { src = W_out; dhi = g_wohi; dlo = g_wolo; off = i4 - 524288; }

    const float4 v = reinterpret_cast<const float4*>(src)[off];
    union { __nv_bfloat16 h[4]; uint2 u; } ph, pl;
    bsplit(v.x, ph.h[0], pl.h[0]); bsplit(v.y, ph.h[1], pl.h[1]);
    bsplit(v.z, ph.h[2], pl.h[2]); bsplit(v.w, ph.h[3], pl.h[3]);
    reinterpret_cast<uint2*>(dhi)[off] = ph.u;
    reinterpret_cast<uint2*>(dlo)[off] = pl.u;
}

// ---------------------------------------------------------------------------
// cp.async double-buffered wmma GEMM (bf16 3-term compensation), 8 warps.
// Tile 64x64, 256 threads, warp tile 16(M)x32(N), K-chunk 32.
// ---------------------------------------------------------------------------
#define PITCH 40
#define TILE_B (64 * PITCH * 2)          // 5120 B
#define AHI_O 0
#define ALO_O (TILE_B)
#define BHI_O (2 * TILE_B)
#define BLO_O (3 * TILE_B)
#define BUF_B (4 * TILE_B)               // 20480 B per stage
#define SMEM_BYTES (2 * BUF_B)           // 40960 B

template <bool CONCAT>
__device__ __forceinline__ void issue_chunk(
    uint32_t sb,
    const __nv_bfloat16* __restrict__ Ahi, const __nv_bfloat16* __restrict__ Alo,
    const __nv_bfloat16* __restrict__ A2hi, const __nv_bfloat16* __restrict__ A2lo,
    const __nv_bfloat16* __restrict__ Bhi, const __nv_bfloat16* __restrict__ Blo,
    int ldb, int m0, int n0, int k0, int tid)
{
    const __nv_bfloat16* ah = Ahi;
    const __nv_bfloat16* al = Alo;
    int koff = k0;
    if (CONCAT && k0 >= H_) { ah = A2hi; al = A2lo; koff = k0 - H_; }
    const int row = tid >> 2, seg = tid & 3;       // 64 rows x 4 x 16B
    const uint32_t soff = (uint32_t)(row * (PITCH * 2) + seg * 16);
    const size_t aoff = (size_t)(m0 + row) * H_ + koff + seg * 8;
    const size_t boff = (size_t)(n0 + row) * ldb + k0 + seg * 8;
    cpa16(sb + AHI_O + soff, ah + aoff);
    cpa16(sb + ALO_O + soff, al + aoff);
    cpa16(sb + BHI_O + soff, Bhi + boff);
    cpa16(sb + BLO_O + soff, Blo + boff);
}

template <bool OUTMODE, bool CONCAT>
__device__ __forceinline__ void gemm_wmma(
    char* smem,
    const __nv_bfloat16* __restrict__ Ahi, const __nv_bfloat16* __restrict__ Alo,
    const __nv_bfloat16* __restrict__ A2hi, const __nv_bfloat16* __restrict__ A2lo,
    const __nv_bfloat16* __restrict__ Bhi, const __nv_bfloat16* __restrict__ Blo,
    int ldb, const float* __restrict__ bias, float* __restrict__ C,
    int m0, int n0, int Ktot)
{
    const int tid  = threadIdx.x;
    const int wid  = tid >> 5;
    const int lane = tid & 31;
    const int m0w  = (wid >> 1) * 16;    // 4 m-warps x 16 rows
    const int n0w  = (wid & 1) * 32;     // 2 n-warps x 32 cols
    const uint32_t sb = smem_u32(smem);

    wmma::fragment<wmma::accumulator, 16, 16, 16, float> acc[2];
    wmma::fill_fragment(acc[0], 0.0f);
    wmma::fill_fragment(acc[1], 0.0f);

    const int nchunks = Ktot / 32;

    issue_chunk<CONCAT>(sb, Ahi, Alo, A2hi, A2lo, Bhi, Blo, ldb, m0, n0, 0, tid);
    CP_COMMIT();

    #pragma unroll 1
    for (int it = 0; it < nchunks; ++it) {
        if (it + 1 < nchunks) {
            issue_chunk<CONCAT>(sb + ((it + 1) & 1) * BUF_B,
                                Ahi, Alo, A2hi, A2lo, Bhi, Blo,
                                ldb, m0, n0, (it + 1) * 32, tid);
            CP_COMMIT();
            CP_WAIT1();
        } else {
            CP_WAIT0();
        }
        __syncthreads();

        const char* buf = smem + (it & 1) * BUF_B;
        const __nv_bfloat16* sAhi = reinterpret_cast<const __nv_bfloat16*>(buf + AHI_O);
        const __nv_bfloat16* sAlo = reinterpret_cast<const __nv_bfloat16*>(buf + ALO_O);
        const __nv_bfloat16* sBhi = reinterpret_cast<const __nv_bfloat16*>(buf + BHI_O);
        const __nv_bfloat16* sBlo = reinterpret_cast<const __nv_bfloat16*>(buf + BLO_O);

        #pragma unroll
        for (int kf = 0; kf < 2; kf++) {
            const int ko = kf * 16;
            wmma::fragment<wmma::matrix_a, 16, 16, 16, __nv_bfloat16, wmma::row_major> ahi, alo;
            wmma::fragment<wmma::matrix_b, 16, 16, 16, __nv_bfloat16, wmma::col_major> bhi[2], blo[2];
            wmma::load_matrix_sync(ahi, &sAhi[m0w * PITCH + ko], PITCH);
            wmma::load_matrix_sync(alo, &sAlo[m0w * PITCH + ko], PITCH);
            #pragma unroll
            for (int ni = 0; ni < 2; ni++) {
                wmma::load_matrix_sync(bhi[ni], &sBhi[(n0w + 16 * ni) * PITCH + ko], PITCH);
                wmma::load_matrix_sync(blo[ni], &sBlo[(n0w + 16 * ni) * PITCH + ko], PITCH);
            }
            #pragma unroll
            for (int ni = 0; ni < 2; ni++) {
                wmma::mma_sync(acc[ni], ahi, bhi[ni], acc[ni]);
                wmma::mma_sync(acc[ni], ahi, blo[ni], acc[ni]);
                wmma::mma_sync(acc[ni], alo, bhi[ni], acc[ni]);
            }
        }
        __syncthreads();
    }

    if (!OUTMODE) {
        #pragma unroll
        for (int ni = 0; ni < 2; ni++)
            wmma::store_matrix_sync(
                &C[(size_t)(m0 + m0w) * H_ + n0 + n0w + 16 * ni],
                acc[ni], H_, wmma::mem_row_major);
    } else {
        // stage 16x32 per warp (pitch 36), then tanh(x + bias)
        __syncthreads();
        float* stage = reinterpret_cast<float*>(smem) + wid * 16 * 36;
        #pragma unroll
        for (int ni = 0; ni < 2; ni++)
            wmma::store_matrix_sync(&stage[16 * ni], acc[ni], 36, wmma::mem_row_major);
        __syncwarp();
        const int r    = lane & 15;              // row in warp tile
        const int coff = (lane >> 4) * 16;       // 0 or 16
        const int m = m0 + m0w + r;
        float* Crow = C + (size_t)m * H_ + n0 + n0w + coff;
        const float* brow = bias + n0 + n0w + coff;
        #pragma unroll
        for (int q = 0; q < 4; q++) {
            const float4 s = *reinterpret_cast<const float4*>(&stage[r * 36 + coff + q * 4]);
            const float4 bb = *reinterpret_cast<const float4*>(&brow[q * 4]);
            float4 o;
            asm("tanh.approx.f32 %0, %1;" : "=f"(o.x) : "f"(s.x + bb.x));
            asm("tanh.approx.f32 %0, %1;" : "=f"(o.y) : "f"(s.y + bb.y));
            asm("tanh.approx.f32 %0, %1;" : "=f"(o.z) : "f"(s.z + bb.z));
            asm("tanh.approx.f32 %0, %1;" : "=f"(o.w) : "f"(s.w + bb.w));
            *reinterpret_cast<float4*>(Crow + q * 4) = o;
        }
    }
}

// proj: grid (8, 48). y<16 -> qs; else hs
__global__ void __launch_bounds__(256) proj_wmma()
{
    __shared__ __align__(16) char smem[SMEM_BYTES];
    const int n0 = blockIdx.x * 64;
    const int my = blockIdx.y;
    if (my < 16)
        gemm_wmma<false, false>(smem, g_qhi, g_qlo, nullptr, nullptr,
                                g_wshi, g_wslo, H_, nullptr, g_qs, my * 64, n0, H_);
    else
        gemm_wmma<false, false>(smem, g_ehi, g_elo, nullptr, nullptr,
                                g_whhi, g_whlo, H_, nullptr, g_hs, (my - 16) * 64, n0, H_);
}

// out: grid (8, 16). out = tanh([ctx|query] @ W_out^T + b), K=1024
__global__ void __launch_bounds__(256) out_wmma(
    const float* __restrict__ b_out, float* __restrict__ out)
{
    __shared__ __align__(16) char smem[SMEM_BYTES];
    gemm_wmma<true, true>(smem, g_chi, g_clo, g_qhi, g_qlo,
                          g_wohi, g_wolo, 2 * H_, b_out, out,
                          blockIdx.y * 64, blockIdx.x * 64, 2 * H_);
}

// ---------------------------------------------------------------------------
// Fused attention, TT=8, length-aware: pass1 skips s >= len chunks,
// pass2 splits [0,len) evenly. ctx emitted as bf16 hi/lo.
// ---------------------------------------------------------------------------
#define TT 8
#define SC 16

__global__ void __launch_bounds__(256) attn_kernel(
    const float* __restrict__ enc, const float* __restrict__ v,
    const int* __restrict__ lens)
{
    __shared__ float sh_hs[SC * H_];          // 32 KB (reused for pass-2 combine)
    __shared__ float sh_sc[TT][S_];           // 8 KB
    __shared__ float sh_rsum[TT];

    const int b    = blockIdx.y;
    const int t0   = blockIdx.x * TT;
    const int tid  = threadIdx.x;
    const int lane = tid & 31;
    const int wid  = tid >> 5;                // one warp per t row

    const int len = lens[b];
    const int nch = (len + SC - 1) / SC;      // 8..16 chunks

    float qreg[16], vreg[16];
    {
        const float* qrow = g_qs + (size_t)(b * T_ + t0 + wid) * H_;
        #pragma unroll
        for (int j = 0; j < 16; j++) {
            qreg[j] = qrow[lane + 32 * j];
            vreg[j] = v[lane + 32 * j];
        }
    }

    const float* hsb  = g_hs + (size_t)b * S_ * H_;
    const float* encb = enc  + (size_t)b * S_ * H_;

    // ---- Pass 1: scores (only chunks with s < len), register prefetch ----
    float4 r[8];
    #pragma unroll
    for (int q = 0; q < 8; q++)
        r[q] = *reinterpret_cast<const float4*>(&hsb[(q * 256 + tid) * 4]);

    #pragma unroll 1
    for (int it = 0; it < nch; ++it) {
        #pragma unroll
        for (int q = 0; q < 8; q++)
            *reinterpret_cast<float4*>(&sh_hs[(q * 256 + tid) * 4]) = r[q];
        __syncthreads();

        if (it + 1 < nch) {
            const float* nxt = &hsb[(size_t)(it + 1) * SC * H_];
            #pragma unroll
            for (int q = 0; q < 8; q++)
                r[q] = *reinterpret_cast<const float4*>(&nxt[(q * 256 + tid) * 4]);
        }

        const int s0 = it * SC;
        #pragma unroll
        for (int i = 0; i < SC; i++) {
            const float* hrow = &sh_hs[i * H_];
            float acc = 0.f;
            #pragma unroll
            for (int j = 0; j < 16; j++) {
                const float x = qreg[j] + hrow[lane + 32 * j];
                float th;
                asm("tanh.approx.f32 %0, %1;" : "=f"(th) : "f"(x));
                acc = fmaf(th, vreg[j], acc);
            }
            acc += __shfl_xor_sync(0xffffffffu, acc, 16);
            acc += __shfl_xor_sync(0xffffffffu, acc, 8);
            acc += __shfl_xor_sync(0xffffffffu, acc, 4);
            acc += __shfl_xor_sync(0xffffffffu, acc, 2);
            acc += __shfl_xor_sync(0xffffffffu, acc, 1);
            if (lane == 0) sh_sc[wid][s0 + i] = acc;
        }
        __syncthreads();
    }

    // ---- Softmax (warp per t row) ----
    {
        const int t = wid;
        float vals[S_ / 32];
        float m = -1e30f;
        #pragma unroll
        for (int i = 0; i < S_ / 32; i++) {
            const int s = lane + 32 * i;
            const float sc = (s < len) ? sh_sc[t][s] : -1e30f;
            vals[i] = sc;
            m = fmaxf(m, sc);
        }
        #pragma unroll
        for (int o = 16; o; o >>= 1) m = fmaxf(m, __shfl_xor_sync(0xffffffffu, m, o));
        float sum = 0.f;
        #pragma unroll
        for (int i = 0; i < S_ / 32; i++) {
            const int s = lane + 32 * i;
            const float e = (s < len) ? __expf(vals[i] - m) : 0.f;
            sh_sc[t][s] = e;
            sum += e;
        }
        #pragma unroll
        for (int o = 16; o; o >>= 1) sum += __shfl_xor_sync(0xffffffffu, sum, o);
        if (lane == 0) sh_rsum[t] = 1.0f / sum;
    }
    __syncthreads();

    // ---- Pass 2: context over s in [0,len), split evenly across halves ----
    const int g  = tid >> 7;
    const int c4 = tid & 127;
    const int half = len >> 1;
    const int sbeg = g ? half : 0;
    const int send = g ? len : half;

    float4 acc4[TT];
    #pragma unroll
    for (int t = 0; t < TT; t++) acc4[t] = make_float4(0.f, 0.f, 0.f, 0.f);

    #pragma unroll 4
    for (int s = sbeg; s < send; s++) {
        const float4 e4 = *reinterpret_cast<const float4*>(&encb[(size_t)s * H_ + c4 * 4]);
        #pragma unroll
        for (int t = 0; t < TT; t++) {
            const float w = sh_sc[t][s];
            acc4[t].x = fmaf(w, e4.x, acc4[t].x);
            acc4[t].y = fmaf(w, e4.y, acc4[t].y);
            acc4[t].z = fmaf(w, e4.z, acc4[t].z);
            acc4[t].w = fmaf(w, e4.w, acc4[t].w);
        }
    }

    if (g == 0) {
        #pragma unroll
        for (int t = 0; t < TT; t++)
            *reinterpret_cast<float4*>(&sh_hs[(t * 128 + c4) * 4]) = acc4[t];
    }
    __syncthreads();
    if (g == 1) {
        #pragma unroll
        for (int t = 0; t < TT; t++) {
            float4 o = *reinterpret_cast<const float4*>(&sh_hs[(t * 128 + c4) * 4]);
            const float rs = sh_rsum[t];
            o.x = (o.x + acc4[t].x) * rs;
            o.y = (o.y + acc4[t].y) * rs;
            o.z = (o.z + acc4[t].z) * rs;
            o.w = (o.w + acc4[t].w) * rs;
            union { __nv_bfloat16 h[4]; uint2 u; } ph, pl;
            bsplit(o.x, ph.h[0], pl.h[0]); bsplit(o.y, ph.h[1], pl.h[1]);
            bsplit(o.z, ph.h[2], pl.h[2]); bsplit(o.w, ph.h[3], pl.h[3]);
            const size_t off = (size_t)(b * T_ + t0 + t) * H_ + c4 * 4;
            *reinterpret_cast<uint2*>(&g_chi[off]) = ph.u;
            *reinterpret_cast<uint2*>(&g_clo[off]) = pl.u;
        }
    }
}

// ---------------------------------------------------------------------------
extern "C" void kernel_launch(void* const* d_in, const int* in_sizes, int n_in,
                              void* d_out, int out_size)
{
    const float* query = (const float*)d_in[0];
    const float* enc   = (const float*)d_in[1];
    const int*   lens  = (const int*)d_in[2];
    const float* W_s   = (const float*)d_in[3];
    const float* W_h   = (const float*)d_in[4];
    const float* v     = (const float*)d_in[5];
    const float* W_out = (const float*)d_in[6];
    const float* b_out = (const float*)d_in[7];
    float* out = (float*)d_out;

    convert_kernel<<<2560, 256>>>(query, enc, W_s, W_h, W_out);
    proj_wmma<<<dim3(8, 48), 256>>>();
    attn_kernel<<<dim3(T_ / TT, B_), 256>>>(enc, v, lens);
    out_wmma<<<dim3(8, 16), 256>>>(b_out, out);
}